// round 8
// baseline (speedup 1.0000x reference)
#include <cuda_runtime.h>
#include <cuda_bf16.h>
#include <cstdint>

#define NN 100000
#define NE 400000
#define NG 4096
#define DD 128
#define HH 256
#define NL 20
#define G_EPS 1e-7f
#define BNEPS 1e-5f

#if defined(__CUDA_ARCH__) && defined(__CUDA_ARCH_FEAT_SM103_ALL)
#define USE_TCGEN05 1
#else
#define USE_TCGEN05 0
#endif

// ---------------- scratch (static device memory; no allocation) ----------------
__device__ float g_hA[(size_t)NN * DD];
__device__ float g_hB[(size_t)NN * DD];
__device__ float g_hh[(size_t)NN * DD];
__device__ float g_y1[(size_t)NN * HH];
__device__ float g_y2[(size_t)NN * HH];
__device__ int   g_deg[NN];
__device__ int   g_rowptr[NN + 1];
__device__ int   g_cursor[NN];
__device__ int   g_eids[NE];
__device__ float g_st1S[HH], g_st1Q[HH];
__device__ float g_st2S[HH], g_st2Q[HH];
__device__ float g_stHS[DD], g_stHQ[DD];
__device__ float g_bnAh[DD], g_bnBh[DD];
__device__ float g_bnA1[HH], g_bnB1[HH];
__device__ float g_bnA2[HH], g_bnB2[HH];
__device__ float g_hg[(size_t)NG * DD];
__device__ float g_cnt[NG];
// pre-split transposed weights: [L][N][K] bf16 hi/lo
__device__ __align__(16) __nv_bfloat16 g_w1hi[(size_t)NL * HH * DD];
__device__ __align__(16) __nv_bfloat16 g_w1lo[(size_t)NL * HH * DD];
__device__ __align__(16) __nv_bfloat16 g_w2hi[(size_t)NL * HH * HH];
__device__ __align__(16) __nv_bfloat16 g_w2lo[(size_t)NL * HH * HH];
__device__ __align__(16) __nv_bfloat16 g_w3hi[(size_t)NL * DD * HH];
__device__ __align__(16) __nv_bfloat16 g_w3lo[(size_t)NL * DD * HH];

// ================= helpers =================
static __device__ __forceinline__ uint32_t smem_u32(const void* p) {
    uint32_t a;
    asm("{ .reg .u64 t; cvta.to.shared.u64 t, %1; cvt.u32.u64 %0, t; }" : "=r"(a) : "l"(p));
    return a;
}
#define SWZ128(o) ((o) ^ (((o) >> 3) & 0x70))

static __device__ __forceinline__ uint32_t pack_bf16(float a, float b) {
    __nv_bfloat162 v = __floats2bfloat162_rn(a, b);
    return *reinterpret_cast<uint32_t*>(&v);
}

// mma.sync bf16 m16n8k16 (fallback path; compiles on plain compute_103)
static __device__ __forceinline__ void mma16816(float* c, const uint32_t* a,
                                                uint32_t b0, uint32_t b1) {
    asm volatile(
        "mma.sync.aligned.m16n8k16.row.col.f32.bf16.bf16.f32 "
        "{%0,%1,%2,%3}, {%4,%5,%6,%7}, {%8,%9}, {%0,%1,%2,%3};"
        : "+f"(c[0]), "+f"(c[1]), "+f"(c[2]), "+f"(c[3])
        : "r"(a[0]), "r"(a[1]), "r"(a[2]), "r"(a[3]), "r"(b0), "r"(b1));
}

#if USE_TCGEN05
static __device__ __forceinline__ uint32_t elect_one_pred() {
    uint32_t pred;
    asm volatile("{\n\t.reg .pred p;\n\telect.sync _|p, 0xFFFFFFFF;\n\tselp.b32 %0, 1, 0, p;\n\t}"
                 : "=r"(pred));
    return pred;
}
static constexpr uint64_t DESC_BASE_SW128 =
    (uint64_t(2) << 61) | (uint64_t(1) << 46) | (uint64_t(64) << 32) | (uint64_t(1) << 16);
#define MAKE_DESC(addr) (DESC_BASE_SW128 | ((uint64_t)((addr) >> 4) & 0x3FFF))
#define MBAR_INIT(a, c) \
    asm volatile("mbarrier.init.shared.b64 [%0], %1;" :: "r"((uint32_t)(a)), "r"((uint32_t)(c)) : "memory")
#define MBAR_WAIT(a, p) do { \
    uint32_t _m = (uint32_t)(a), _p = (uint32_t)(p), _d; \
    asm volatile("{\n\t.reg .pred q;\n\tmbarrier.try_wait.parity.acquire.cta.shared::cta.b64 q, [%1], %2;\n\tselp.b32 %0, 1, 0, q;\n\t}" \
                 : "=r"(_d) : "r"(_m), "r"(_p) : "memory"); \
    if (!_d) { \
        asm volatile("{\n\t.reg .pred Q;\n\tWL_%=:\n\tmbarrier.try_wait.parity.acquire.cta.shared::cta.b64 Q, [%0], %1, 0x989680;\n\t@Q bra.uni WD_%=;\n\tbra.uni WL_%=;\n\tWD_%=:\n\t}" \
                     :: "r"(_m), "r"(_p) : "memory"); \
    } \
} while (0)
#define TC_ALLOC(sa, n) \
    asm volatile("tcgen05.alloc.cta_group::1.sync.aligned.shared::cta.b32 [%0], %1;" \
                 :: "r"((uint32_t)(sa)), "r"((uint32_t)(n)) : "memory")
#define TC_DEALLOC(t, n) \
    asm volatile("tcgen05.dealloc.cta_group::1.sync.aligned.b32 %0, %1;" :: "r"(t), "r"((uint32_t)(n)))
#define TC_RELINQ() asm volatile("tcgen05.relinquish_alloc_permit.cta_group::1.sync.aligned;")
#define TC_COMMIT(a) \
    asm volatile("tcgen05.commit.cta_group::1.mbarrier::arrive::one.shared::cluster.b64 [%0];" \
                 :: "r"((uint32_t)(a)) : "memory")
#define TC_FENCE_AFTER() asm volatile("tcgen05.fence::after_thread_sync;" ::: "memory")
#define FENCE_ASYNC() asm volatile("fence.proxy.async.shared::cta;" ::: "memory")
#define TC_WAIT_LD() asm volatile("tcgen05.wait::ld.sync.aligned;" ::: "memory")

static __device__ __forceinline__ void mma_f16_ss(uint32_t d, uint64_t ad, uint64_t bd,
                                                  uint32_t idesc, uint32_t en) {
    asm volatile(
        "{\n\t.reg .pred p;\n\tsetp.ne.u32 p, %4, 0;\n\t"
        "tcgen05.mma.cta_group::1.kind::f16 [%0], %1, %2, %3, {%5, %5, %5, %5}, p;\n\t}"
        :: "r"(d), "l"(ad), "l"(bd), "r"(idesc), "r"(en), "r"(0u) : "memory");
}
#define TC_LD_X32(r, a) \
    asm volatile( \
        "tcgen05.ld.sync.aligned.32x32b.x32.b32 " \
        "{%0, %1, %2, %3, %4, %5, %6, %7, %8, %9, %10, %11, %12, %13, %14, %15, " \
        " %16, %17, %18, %19, %20, %21, %22, %23, %24, %25, %26, %27, %28, %29, %30, %31}, [%32];" \
        : "=r"((r)[0]), "=r"((r)[1]), "=r"((r)[2]), "=r"((r)[3]), "=r"((r)[4]), "=r"((r)[5]), \
          "=r"((r)[6]), "=r"((r)[7]), "=r"((r)[8]), "=r"((r)[9]), "=r"((r)[10]), "=r"((r)[11]), \
          "=r"((r)[12]), "=r"((r)[13]), "=r"((r)[14]), "=r"((r)[15]), "=r"((r)[16]), "=r"((r)[17]), \
          "=r"((r)[18]), "=r"((r)[19]), "=r"((r)[20]), "=r"((r)[21]), "=r"((r)[22]), "=r"((r)[23]), \
          "=r"((r)[24]), "=r"((r)[25]), "=r"((r)[26]), "=r"((r)[27]), "=r"((r)[28]), "=r"((r)[29]), \
          "=r"((r)[30]), "=r"((r)[31]) \
        : "r"(a))
#endif  // USE_TCGEN05

// ---------------- atom encoder ----------------
__global__ void atom_kernel(const int* __restrict__ x, const float* __restrict__ emb,
                            float* __restrict__ h) {
    int n = blockIdx.x, c = threadIdx.x;
    __shared__ int xi[9];
    if (c < 9) xi[c] = x[n * 9 + c];
    __syncthreads();
    float s = 0.f;
#pragma unroll
    for (int i = 0; i < 9; i++) s += emb[((size_t)i * 119 + xi[i]) * DD + c];
    h[(size_t)n * DD + c] = s;
}

// ---------------- CSR build ----------------
__global__ void hist_kernel(const int* __restrict__ dst, int* __restrict__ deg) {
    int e = blockIdx.x * blockDim.x + threadIdx.x;
    if (e < NE) atomicAdd(&deg[dst[e]], 1);
}

__global__ void scan_kernel(const int* __restrict__ deg, int* __restrict__ rowptr,
                            int* __restrict__ cursor) {
    __shared__ int sums[1024];
    int tid = threadIdx.x;
    const int CH = (NN + 1023) / 1024;
    int start = tid * CH;
    int s = 0;
    for (int i = 0; i < CH; i++) {
        int idx = start + i;
        if (idx < NN) s += deg[idx];
    }
    sums[tid] = s;
    __syncthreads();
    for (int off = 1; off < 1024; off <<= 1) {
        int v = (tid >= off) ? sums[tid - off] : 0;
        __syncthreads();
        sums[tid] += v;
        __syncthreads();
    }
    int run = (tid == 0) ? 0 : sums[tid - 1];
    for (int i = 0; i < CH; i++) {
        int idx = start + i;
        if (idx < NN) {
            rowptr[idx] = run;
            cursor[idx] = run;
            run += deg[idx];
        }
    }
    if (tid == 1023) rowptr[NN] = sums[1023];
}

__global__ void scatter_kernel(const int* __restrict__ dst, int* __restrict__ cursor,
                               int* __restrict__ eids) {
    int e = blockIdx.x * blockDim.x + threadIdx.x;
    if (e < NE) {
        int pos = atomicAdd(&cursor[dst[e]], 1);
        eids[pos] = e;
    }
}

// ---------------- GENConv aggregation (one warp per node, online softmax) ----------------
__global__ __launch_bounds__(256) void agg_kernel(
    const float* __restrict__ h, const float* __restrict__ bnA, const float* __restrict__ bnB,
    const int* __restrict__ src, const int* __restrict__ eattr,
    const int* __restrict__ rowptr, const int* __restrict__ eids,
    const float* __restrict__ bond, const float* __restrict__ tptr, int layer,
    float* __restrict__ hh) {
    __shared__ float sb[3 * 6 * DD];
    int tid = threadIdx.x;
    for (int i = tid; i < 3 * 6 * DD; i += blockDim.x) sb[i] = bond[i];
    __syncthreads();
    float t = __ldg(&tptr[layer]);
    int warp = blockIdx.x * (blockDim.x >> 5) + (tid >> 5);
    if (warp >= NN) return;
    int lane = tid & 31;
    bool hasBn = (bnA != nullptr);

    float A[4], B[4], h2n[4];
#pragma unroll
    for (int u = 0; u < 4; u++) {
        int c = lane + 32 * u;
        float a = hasBn ? bnA[c] : 1.f;
        float b = hasBn ? bnB[c] : 0.f;
        A[u] = a; B[u] = b;
        float v = h[(size_t)warp * DD + c];
        if (hasBn) v = fmaxf(v * a + b, 0.f);
        h2n[u] = v;
    }
    const float NEGINF = __int_as_float(0xff800000);
    float m[4] = {NEGINF, NEGINF, NEGINF, NEGINF};
    float s1[4] = {0.f, 0.f, 0.f, 0.f};
    float s2[4] = {0.f, 0.f, 0.f, 0.f};
    int e0 = rowptr[warp], e1 = rowptr[warp + 1];
    for (int e = e0; e < e1; e++) {
        int eid = eids[e];
        int s = src[eid];
        int a0 = eattr[eid * 3 + 0];
        int a1 = eattr[eid * 3 + 1];
        int a2 = eattr[eid * 3 + 2];
        const float* hs = h + (size_t)s * DD;
#pragma unroll
        for (int u = 0; u < 4; u++) {
            int c = lane + 32 * u;
            float hv = hs[c];
            if (hasBn) hv = fmaxf(hv * A[u] + B[u], 0.f);
            float ee = sb[a0 * DD + c] + sb[(6 + a1) * DD + c] + sb[(12 + a2) * DD + c];
            float msg = fmaxf(hv + ee, 0.f) + G_EPS;
            float sc = msg * t;
            if (sc > m[u]) {
                float r = __expf(m[u] - sc);
                s1[u] = s1[u] * r + 1.f;
                s2[u] = s2[u] * r + msg;
                m[u] = sc;
            } else {
                float ex = __expf(sc - m[u]);
                s1[u] += ex;
                s2[u] += msg * ex;
            }
        }
    }
#pragma unroll
    for (int u = 0; u < 4; u++) {
        float mm = s2[u] / fmaxf(s1[u], G_EPS);
        hh[(size_t)warp * DD + lane + 32 * u] = h2n[u] + mm;
    }
}

// ---------------- weight pre-transpose + bf16 hi/lo split ----------------
__global__ void splitw_kernel(const float* __restrict__ W, int K, int N, int total,
                              __nv_bfloat16* __restrict__ hiT, __nv_bfloat16* __restrict__ loT) {
    int i = blockIdx.x * blockDim.x + threadIdx.x;
    if (i >= total) return;
    int n = i % N;
    int k = (i / N) % K;
    int l = i / (N * K);
    float w = W[i];
    __nv_bfloat16 hi = __float2bfloat16_rn(w);
    float lo = w - __bfloat162float(hi);
    size_t o = ((size_t)l * N + n) * K + k;
    hiT[o] = hi;
    loT[o] = __float2bfloat16_rn(lo);
}

// ---------------- shared staging: fp32 A -> (BN+relu) -> bf16 hi/lo swizzled SMEM ----------
// Layout from tile base (offA): Ahi[16K] Alo[16K] Bhi[N*128] Blo[N*128]
#define KC 64
#define TILE_OFF 4096

template <int N>
static __device__ __forceinline__ void stage_tile(
    char* base, uint32_t offA, const float* arp, bool rowValid,
    const __nv_bfloat16* __restrict__ BThi, const __nv_bfloat16* __restrict__ BTlo,
    const float* trASm, const float* trBSm, bool hasTr, int k0, int K, int t) {
    const uint32_t offAlo = offA + 16384;
    const uint32_t offBhi = offA + 32768;
    const uint32_t offBlo = offBhi + (uint32_t)N * 128;
    const int arow = t >> 1;
    const int acol0 = (t & 1) * 32;
    // A: load fp32, transform, split, swizzled STS
    {
        float av[32];
        if (rowValid) {
#pragma unroll
            for (int g = 0; g < 8; g++) {
                float4 v = *(const float4*)(arp + k0 + acol0 + g * 4);
                av[g * 4 + 0] = v.x; av[g * 4 + 1] = v.y;
                av[g * 4 + 2] = v.z; av[g * 4 + 3] = v.w;
            }
            if (hasTr) {
#pragma unroll
                for (int j = 0; j < 32; j++) {
                    int kg = k0 + acol0 + j;
                    av[j] = fmaxf(av[j] * trASm[kg] + trBSm[kg], 0.f);
                }
            }
        } else {
#pragma unroll
            for (int j = 0; j < 32; j++) av[j] = 0.f;
        }
        uint32_t hp[16], lp[16];
#pragma unroll
        for (int p = 0; p < 16; p++) {
            float a0 = av[2 * p], a1 = av[2 * p + 1];
            float h0 = __bfloat162float(__float2bfloat16_rn(a0));
            float h1 = __bfloat162float(__float2bfloat16_rn(a1));
            hp[p] = pack_bf16(h0, h1);
            lp[p] = pack_bf16(a0 - h0, a1 - h1);
        }
        uint32_t ro = (uint32_t)arow * 128 + (uint32_t)acol0 * 2;
#pragma unroll
        for (int g = 0; g < 4; g++) {
            uint32_t sw = SWZ128(ro + g * 16);
            *(uint4*)(base + offA + sw) =
                make_uint4(hp[4 * g], hp[4 * g + 1], hp[4 * g + 2], hp[4 * g + 3]);
            *(uint4*)(base + offAlo + sw) =
                make_uint4(lp[4 * g], lp[4 * g + 1], lp[4 * g + 2], lp[4 * g + 3]);
        }
    }
    // B: copy pre-split bf16 rows (one row per thread), swizzled STS
    if (t < N) {
        const uint4* bh = (const uint4*)(BThi + (size_t)t * K + k0);
        const uint4* bl = (const uint4*)(BTlo + (size_t)t * K + k0);
        uint32_t ro = (uint32_t)t * 128;
#pragma unroll
        for (int g = 0; g < 8; g++) {
            uint32_t sw = SWZ128(ro + g * 16);
            *(uint4*)(base + offBhi + sw) = bh[g];
            *(uint4*)(base + offBlo + sw) = bl[g];
        }
    }
}

// ---------------- tensor GEMM: C[M,N] = f(A)[M,K] @ BT^T + bias (+res), stats fused ----------
// Full-N tile (grid.x == 1): A read exactly once. Serial tcgen05 per-chunk pipeline:
// stage -> fence -> sync -> elect MMA (3-pass bf16 split) -> commit -> parity wait.
template <int K, int N>
__global__ __launch_bounds__(256) void tgemm_kernel(
    const float* __restrict__ A, const __nv_bfloat16* __restrict__ BThi,
    const __nv_bfloat16* __restrict__ BTlo, const float* __restrict__ bias,
    const float* __restrict__ trA, const float* __restrict__ trB,
    const float* __restrict__ res, float* __restrict__ C,
    float* __restrict__ statS, float* __restrict__ statQ) {
    extern __shared__ char smem_raw[];
    uint32_t sb0 = smem_u32(smem_raw);
    uint32_t ab = (sb0 + 1023u) & ~1023u;
    char* base = smem_raw + (ab - sb0);
    float* biasSm = (float*)(base + 32);
    float* trASm = (float*)(base + 1056);
    float* trBSm = (float*)(base + 2080);

    const int t = threadIdx.x;
    constexpr int nc = K / KC;
    const bool hasTr = (trA != nullptr);
    const int growBase = blockIdx.y * 128;
    const int grow = growBase + (t >> 1);
    const float* arp = A + (size_t)grow * K;
    const bool rowValid = (grow < NN);

    if (t < N) biasSm[t] = bias[t];
    if (hasTr && t < K) { trASm[t] = trA[t]; trBSm[t] = trB[t]; }

#if USE_TCGEN05
    constexpr uint32_t idesc = 0x490u | ((uint32_t)(N / 8) << 17) | (8u << 24);
    if ((t >> 5) == 0) TC_ALLOC(ab, N);      // only N TMEM cols -> 2 CTAs/SM possible
    if (t == 0) MBAR_INIT(ab + 8, 1);
    __syncthreads();
    uint32_t tmem;
    asm volatile("ld.shared.b32 %0, [%1];" : "=r"(tmem) : "r"(ab));

    for (int c = 0; c < nc; c++) {
        stage_tile<N>(base, TILE_OFF, arp, rowValid, BThi, BTlo, trASm, trBSm, hasTr,
                      c * KC, K, t);
        FENCE_ASYNC();
        __syncthreads();
        if ((t >> 5) == 0) {
            if (elect_one_pred()) {
                uint32_t stA = ab + TILE_OFF;
                uint64_t dah = MAKE_DESC(stA), dal = MAKE_DESC(stA + 16384);
                uint64_t dbh = MAKE_DESC(stA + 32768);
                uint64_t dbl = MAKE_DESC(stA + 32768 + N * 128);
#pragma unroll
                for (int kk = 0; kk < 4; kk++)
                    mma_f16_ss(tmem, dah + kk * 2, dbh + kk * 2, idesc, (c || kk) ? 1u : 0u);
#pragma unroll
                for (int kk = 0; kk < 4; kk++)
                    mma_f16_ss(tmem, dah + kk * 2, dbl + kk * 2, idesc, 1u);
#pragma unroll
                for (int kk = 0; kk < 4; kk++)
                    mma_f16_ss(tmem, dal + kk * 2, dbh + kk * 2, idesc, 1u);
                TC_COMMIT(ab + 8);
            }
        }
        MBAR_WAIT(ab + 8, c & 1);   // serial: all threads wait; SMEM safe to restage
    }
    TC_FENCE_AFTER();

    // epilogue: TMEM -> bias/res/store + column stats (smem-transpose reduction)
    if (t < 128) {
        int lane = t & 31;
        int row = growBase + (t >> 5) * 32 + lane;
        bool rv = (row < NN);
        bool doStat = (statS != nullptr);
        float* tb = (float*)(base + TILE_OFF) + (t >> 5) * (32 * 33);
#pragma unroll
        for (int cb = 0; cb < N / 32; cb++) {
            uint32_t r[32];
            TC_LD_X32(r, tmem + cb * 32);
            TC_WAIT_LD();
            float v[32];
#pragma unroll
            for (int j = 0; j < 32; j++) v[j] = __uint_as_float(r[j]) + biasSm[cb * 32 + j];
            if (res != nullptr && rv) {
                const float* rr = res + (size_t)row * N + cb * 32;
#pragma unroll
                for (int g = 0; g < 8; g++) {
                    float4 q = *(const float4*)(rr + g * 4);
                    v[g * 4 + 0] += q.x; v[g * 4 + 1] += q.y;
                    v[g * 4 + 2] += q.z; v[g * 4 + 3] += q.w;
                }
            }
            if (rv) {
                float* cr = C + (size_t)row * N + cb * 32;
#pragma unroll
                for (int g = 0; g < 8; g++)
                    *(float4*)(cr + g * 4) =
                        make_float4(v[g * 4], v[g * 4 + 1], v[g * 4 + 2], v[g * 4 + 3]);
            }
            if (doStat) {
#pragma unroll
                for (int j = 0; j < 32; j++) tb[j * 33 + lane] = rv ? v[j] : 0.f;
                __syncwarp();
                float s = 0.f, q = 0.f;
#pragma unroll
                for (int r2 = 0; r2 < 32; r2++) {
                    float x = tb[lane * 33 + r2];
                    s += x; q += x * x;
                }
                atomicAdd(&statS[cb * 32 + lane], s);
                atomicAdd(&statQ[cb * 32 + lane], q);
                __syncwarp();
            }
        }
    }
    __syncthreads();
    if ((t >> 5) == 0) {
        TC_RELINQ();
        TC_DEALLOC(tmem, N);
    }
#else
    // ===== fallback (never executes: sm_103a cubin is exact match) — mma.sync from staging =====
    __syncthreads();
    const int warp = t >> 5;
    const int lane = t & 31;
    float acc[N / 8][4];
#pragma unroll
    for (int j = 0; j < N / 8; j++)
#pragma unroll
        for (int q = 0; q < 4; q++) acc[j][q] = 0.f;
    const uint32_t colb = (uint32_t)(lane & 3) * 4;
    const uint32_t rowb = (uint32_t)(warp * 16 + (lane >> 2)) * 128;
    for (int c = 0; c < nc; c++) {
        if (c) __syncthreads();
        stage_tile<N>(base, TILE_OFF, arp, rowValid, BThi, BTlo, trASm, trBSm, hasTr,
                      c * KC, K, t);
        __syncthreads();
#pragma unroll
        for (int kk = 0; kk < 4; kk++) {
            uint32_t kb = kk * 32;
            uint32_t o0 = rowb + kb + colb;
            uint32_t ah[4], al[4];
            ah[0] = *(const uint32_t*)(base + TILE_OFF + SWZ128(o0));
            ah[1] = *(const uint32_t*)(base + TILE_OFF + SWZ128(o0 + 1024));
            ah[2] = *(const uint32_t*)(base + TILE_OFF + SWZ128(o0 + 16));
            ah[3] = *(const uint32_t*)(base + TILE_OFF + SWZ128(o0 + 1024 + 16));
            al[0] = *(const uint32_t*)(base + TILE_OFF + 16384 + SWZ128(o0));
            al[1] = *(const uint32_t*)(base + TILE_OFF + 16384 + SWZ128(o0 + 1024));
            al[2] = *(const uint32_t*)(base + TILE_OFF + 16384 + SWZ128(o0 + 16));
            al[3] = *(const uint32_t*)(base + TILE_OFF + 16384 + SWZ128(o0 + 1024 + 16));
#pragma unroll
            for (int j = 0; j < N / 8; j++) {
                uint32_t ob = (uint32_t)(j * 8 + (lane >> 2)) * 128 + kb + colb;
                uint32_t bh0 = *(const uint32_t*)(base + TILE_OFF + 32768 + SWZ128(ob));
                uint32_t bh1 = *(const uint32_t*)(base + TILE_OFF + 32768 + SWZ128(ob + 16));
                uint32_t bl0 = *(const uint32_t*)(base + TILE_OFF + 32768 + N * 128 + SWZ128(ob));
                uint32_t bl1 = *(const uint32_t*)(base + TILE_OFF + 32768 + N * 128 + SWZ128(ob + 16));
                mma16816(acc[j], ah, bh0, bh1);
                mma16816(acc[j], ah, bl0, bl1);
                mma16816(acc[j], al, bh0, bh1);
            }
        }
    }
    {
        int rA = growBase + warp * 16 + (lane >> 2);
        int rB = rA + 8;
        bool mA = (rA < NN), mB = (rB < NN);
        bool doStat = (statS != nullptr);
#pragma unroll
        for (int j = 0; j < N / 8; j++) {
            int cn = j * 8 + (lane & 3) * 2;
            float v0 = acc[j][0] + biasSm[cn];
            float v1 = acc[j][1] + biasSm[cn + 1];
            float v2 = acc[j][2] + biasSm[cn];
            float v3 = acc[j][3] + biasSm[cn + 1];
            if (res != nullptr) {
                if (mA) { float2 rv = *(const float2*)(res + (size_t)rA * N + cn); v0 += rv.x; v1 += rv.y; }
                if (mB) { float2 rv = *(const float2*)(res + (size_t)rB * N + cn); v2 += rv.x; v3 += rv.y; }
            }
            if (mA) *(float2*)(C + (size_t)rA * N + cn) = make_float2(v0, v1);
            if (mB) *(float2*)(C + (size_t)rB * N + cn) = make_float2(v2, v3);
            if (doStat) {
                float se = (mA ? v0 : 0.f) + (mB ? v2 : 0.f);
                float qe = (mA ? v0 * v0 : 0.f) + (mB ? v2 * v2 : 0.f);
                float so = (mA ? v1 : 0.f) + (mB ? v3 : 0.f);
                float qo = (mA ? v1 * v1 : 0.f) + (mB ? v3 * v3 : 0.f);
#pragma unroll
                for (int off = 4; off < 32; off <<= 1) {
                    se += __shfl_xor_sync(0xffffffffu, se, off);
                    qe += __shfl_xor_sync(0xffffffffu, qe, off);
                    so += __shfl_xor_sync(0xffffffffu, so, off);
                    qo += __shfl_xor_sync(0xffffffffu, qo, off);
                }
                if ((lane >> 2) == 0) {
                    atomicAdd(&statS[cn], se);
                    atomicAdd(&statQ[cn], qe);
                    atomicAdd(&statS[cn + 1], so);
                    atomicAdd(&statQ[cn + 1], qo);
                }
            }
        }
    }
#endif
}

// ---------------- BN stat finalize (+ zero next-stage stat buffers) ----------------
__global__ void finalize_kernel(const float* __restrict__ sum, const float* __restrict__ sq,
                                const float* __restrict__ g, const float* __restrict__ be,
                                float* __restrict__ outA, float* __restrict__ outB, int C,
                                float* __restrict__ z1, float* __restrict__ z2, int zlen) {
    int i = threadIdx.x;
    if (sum != nullptr && i < C) {
        float mu = sum[i] * (1.f / NN);
        float var = sq[i] * (1.f / NN) - mu * mu;
        float inv = rsqrtf(var + BNEPS);
        float a = g[i] * inv;
        outA[i] = a;
        outB[i] = be[i] - mu * a;
    }
    if (z1 != nullptr) {
        for (int j = i; j < zlen; j += blockDim.x) { z1[j] = 0.f; z2[j] = 0.f; }
    }
}

// ---------------- final BN + graph mean pool ----------------
__global__ void pool_kernel(const float* __restrict__ h, const float* __restrict__ bnA,
                            const float* __restrict__ bnB, const int* __restrict__ batch,
                            float* __restrict__ hg, float* __restrict__ cnt) {
    int n = blockIdx.x, c = threadIdx.x;
    int b = batch[n];
    float v = h[(size_t)n * DD + c] * bnA[c] + bnB[c];
    atomicAdd(&hg[(size_t)b * DD + c], v);
    if (c == 0) atomicAdd(&cnt[b], 1.f);
}

__global__ void out_kernel(const float* __restrict__ hg, const float* __restrict__ cnt,
                           const float* __restrict__ predW, const float* __restrict__ predb,
                           float* __restrict__ out) {
    int g = blockIdx.x, c = threadIdx.x;
    float scale = 1.f / fmaxf(cnt[g], 1.f);
    float v = hg[(size_t)g * DD + c] * scale * predW[c];
#pragma unroll
    for (int off = 16; off; off >>= 1) v += __shfl_down_sync(0xffffffffu, v, off);
    __shared__ float ws[4];
    if ((c & 31) == 0) ws[c >> 5] = v;
    __syncthreads();
    if (c == 0) out[g] = ws[0] + ws[1] + ws[2] + ws[3] + predb[0];
}

// ---------------- host orchestration ----------------
extern "C" void kernel_launch(void* const* d_in, const int* in_sizes, int n_in,
                              void* d_out, int out_size) {
    const int*   x        = (const int*)d_in[0];
    const int*   eidx     = (const int*)d_in[1];
    const int*   eattr    = (const int*)d_in[2];
    const int*   batch    = (const int*)d_in[3];
    const float* atom_emb = (const float*)d_in[4];
    const float* bond_emb = (const float*)d_in[5];
    const float* W1 = (const float*)d_in[6];
    const float* b1 = (const float*)d_in[7];
    const float* g1 = (const float*)d_in[8];
    const float* be1 = (const float*)d_in[9];
    const float* W2 = (const float*)d_in[10];
    const float* b2 = (const float*)d_in[11];
    const float* g2 = (const float*)d_in[12];
    const float* be2 = (const float*)d_in[13];
    const float* W3 = (const float*)d_in[14];
    const float* b3 = (const float*)d_in[15];
    const float* tt = (const float*)d_in[16];
    const float* norm_g = (const float*)d_in[17];
    const float* norm_b = (const float*)d_in[18];
    const float* predW = (const float*)d_in[19];
    const float* predb = (const float*)d_in[20];
    float* out = (float*)d_out;

    const int* src = eidx;
    const int* dst = eidx + NE;

    float *hA, *hB, *hh, *y1, *y2;
    int *deg, *rowptr, *cursor, *eids;
    float *st1S, *st1Q, *st2S, *st2Q, *stHS, *stHQ;
    float *bnAh, *bnBh, *bnA1, *bnB1, *bnA2, *bnB2;
    float *hg, *cnt;
    __nv_bfloat16 *w1hi, *w1lo, *w2hi, *w2lo, *w3hi, *w3lo;
    cudaGetSymbolAddress((void**)&hA, g_hA);
    cudaGetSymbolAddress((void**)&hB, g_hB);
    cudaGetSymbolAddress((void**)&hh, g_hh);
    cudaGetSymbolAddress((void**)&y1, g_y1);
    cudaGetSymbolAddress((void**)&y2, g_y2);
    cudaGetSymbolAddress((void**)&deg, g_deg);
    cudaGetSymbolAddress((void**)&rowptr, g_rowptr);
    cudaGetSymbolAddress((void**)&cursor, g_cursor);
    cudaGetSymbolAddress((void**)&eids, g_eids);
    cudaGetSymbolAddress((void**)&st1S, g_st1S);
    cudaGetSymbolAddress((void**)&st1Q, g_st1Q);
    cudaGetSymbolAddress((void**)&st2S, g_st2S);
    cudaGetSymbolAddress((void**)&st2Q, g_st2Q);
    cudaGetSymbolAddress((void**)&stHS, g_stHS);
    cudaGetSymbolAddress((void**)&stHQ, g_stHQ);
    cudaGetSymbolAddress((void**)&bnAh, g_bnAh);
    cudaGetSymbolAddress((void**)&bnBh, g_bnBh);
    cudaGetSymbolAddress((void**)&bnA1, g_bnA1);
    cudaGetSymbolAddress((void**)&bnB1, g_bnB1);
    cudaGetSymbolAddress((void**)&bnA2, g_bnA2);
    cudaGetSymbolAddress((void**)&bnB2, g_bnB2);
    cudaGetSymbolAddress((void**)&hg, g_hg);
    cudaGetSymbolAddress((void**)&cnt, g_cnt);
    cudaGetSymbolAddress((void**)&w1hi, g_w1hi);
    cudaGetSymbolAddress((void**)&w1lo, g_w1lo);
    cudaGetSymbolAddress((void**)&w2hi, g_w2hi);
    cudaGetSymbolAddress((void**)&w2lo, g_w2lo);
    cudaGetSymbolAddress((void**)&w3hi, g_w3hi);
    cudaGetSymbolAddress((void**)&w3lo, g_w3lo);

    const int SM_H = TILE_OFF + 32768 + 2 * HH * 128 + 1024;  // 103424 (N=256)
    const int SM_D = TILE_OFF + 32768 + 2 * DD * 128 + 1024;  // 70656  (N=128)
    cudaFuncSetAttribute(tgemm_kernel<DD, HH>, cudaFuncAttributeMaxDynamicSharedMemorySize, SM_H);
    cudaFuncSetAttribute(tgemm_kernel<HH, HH>, cudaFuncAttributeMaxDynamicSharedMemorySize, SM_H);
    cudaFuncSetAttribute(tgemm_kernel<HH, DD>, cudaFuncAttributeMaxDynamicSharedMemorySize, SM_D);

    // setup: atom encoder + CSR + weight pre-split
    atom_kernel<<<NN, 128>>>(x, atom_emb, hA);
    cudaMemsetAsync(deg, 0, NN * sizeof(int));
    hist_kernel<<<(NE + 255) / 256, 256>>>(dst, deg);
    scan_kernel<<<1, 1024>>>(deg, rowptr, cursor);
    scatter_kernel<<<(NE + 255) / 256, 256>>>(dst, cursor, eids);
    {
        int t1 = NL * DD * HH;
        splitw_kernel<<<(t1 + 255) / 256, 256>>>(W1, DD, HH, t1, w1hi, w1lo);
        int t2 = NL * HH * HH;
        splitw_kernel<<<(t2 + 255) / 256, 256>>>(W2, HH, HH, t2, w2hi, w2lo);
        int t3 = NL * HH * DD;
        splitw_kernel<<<(t3 + 255) / 256, 256>>>(W3, HH, DD, t3, w3hi, w3lo);
    }

    float* hcur = hA;
    float* hnxt = hB;
    const int MBLK = (NN + 127) / 128;  // 782
    dim3 gridT(1, MBLK);

    for (int l = 0; l < NL; l++) {
        finalize_kernel<<<1, 256>>>(l ? stHS : nullptr, stHQ,
                                    l ? norm_g + (size_t)(l - 1) * DD : nullptr,
                                    l ? norm_b + (size_t)(l - 1) * DD : nullptr,
                                    bnAh, bnBh, DD, st1S, st1Q, HH);
        agg_kernel<<<NN / 8, 256>>>(hcur, l ? bnAh : nullptr, l ? bnBh : nullptr,
                                    src, eattr, rowptr, eids,
                                    bond_emb + (size_t)l * 3 * 6 * DD, tt, l, hh);
        tgemm_kernel<DD, HH><<<gridT, 256, SM_H>>>(
            hh, w1hi + (size_t)l * HH * DD, w1lo + (size_t)l * HH * DD, b1 + (size_t)l * HH,
            nullptr, nullptr, nullptr, y1, st1S, st1Q);
        finalize_kernel<<<1, 256>>>(st1S, st1Q, g1 + (size_t)l * HH, be1 + (size_t)l * HH,
                                    bnA1, bnB1, HH, st2S, st2Q, HH);
        tgemm_kernel<HH, HH><<<gridT, 256, SM_H>>>(
            y1, w2hi + (size_t)l * HH * HH, w2lo + (size_t)l * HH * HH, b2 + (size_t)l * HH,
            bnA1, bnB1, nullptr, y2, st2S, st2Q);
        finalize_kernel<<<1, 256>>>(st2S, st2Q, g2 + (size_t)l * HH, be2 + (size_t)l * HH,
                                    bnA2, bnB2, HH, stHS, stHQ, DD);
        tgemm_kernel<HH, DD><<<gridT, 256, SM_D>>>(
            y2, w3hi + (size_t)l * DD * HH, w3lo + (size_t)l * DD * HH, b3 + (size_t)l * DD,
            bnA2, bnB2, l ? hcur : nullptr, hnxt, stHS, stHQ);
        float* tmp = hcur; hcur = hnxt; hnxt = tmp;
    }
    finalize_kernel<<<1, 256>>>(stHS, stHQ, norm_g + (size_t)(NL - 1) * DD,
                                norm_b + (size_t)(NL - 1) * DD, bnAh, bnBh, DD,
                                nullptr, nullptr, 0);
    cudaMemsetAsync(hg, 0, (size_t)NG * DD * sizeof(float));
    cudaMemsetAsync(cnt, 0, NG * sizeof(float));
    pool_kernel<<<NN, 128>>>(hcur, bnAh, bnBh, batch, hg, cnt);
    out_kernel<<<NG, 128>>>(hg, cnt, predW, predb, out);
}

// round 10
// speedup vs baseline: 1.1413x; 1.1413x over previous
#include <cuda_runtime.h>
#include <cuda_bf16.h>
#include <cstdint>

#define NN 100000
#define NE 400000
#define NG 4096
#define DD 128
#define HH 256
#define NL 20
#define G_EPS 1e-7f
#define BNEPS 1e-5f

// ---------------- scratch (static device memory; no allocation) ----------------
__device__ float g_hA[(size_t)NN * DD];
__device__ float g_hB[(size_t)NN * DD];
__device__ float g_hh[(size_t)NN * DD];
__device__ float g_y1[(size_t)NN * HH];
__device__ float g_y2[(size_t)NN * HH];
__device__ int   g_deg[NN];
__device__ int   g_rowptr[NN + 1];
__device__ int   g_cursor[NN];
__device__ int   g_eids[NE];
__device__ float g_st1S[HH], g_st1Q[HH];
__device__ float g_st2S[HH], g_st2Q[HH];
__device__ float g_stHS[DD], g_stHQ[DD];
__device__ float g_bnAh[DD], g_bnBh[DD];
__device__ float g_bnA1[HH], g_bnB1[HH];
__device__ float g_bnA2[HH], g_bnB2[HH];
__device__ float g_hg[(size_t)NG * DD];
__device__ float g_cnt[NG];
// pre-split transposed weights: [L][N][K] bf16 hi/lo
__device__ __align__(16) __nv_bfloat16 g_w1hi[(size_t)NL * HH * DD];
__device__ __align__(16) __nv_bfloat16 g_w1lo[(size_t)NL * HH * DD];
__device__ __align__(16) __nv_bfloat16 g_w2hi[(size_t)NL * HH * HH];
__device__ __align__(16) __nv_bfloat16 g_w2lo[(size_t)NL * HH * HH];
__device__ __align__(16) __nv_bfloat16 g_w3hi[(size_t)NL * DD * HH];
__device__ __align__(16) __nv_bfloat16 g_w3lo[(size_t)NL * DD * HH];

// ================= helpers =================
static __device__ __forceinline__ uint32_t pack_bf16(float a, float b) {
    __nv_bfloat162 v = __floats2bfloat162_rn(a, b);
    return *reinterpret_cast<uint32_t*>(&v);
}

static __device__ __forceinline__ void mma16816(float* c, const uint32_t* a,
                                                uint32_t b0, uint32_t b1) {
    asm volatile(
        "mma.sync.aligned.m16n8k16.row.col.f32.bf16.bf16.f32 "
        "{%0,%1,%2,%3}, {%4,%5,%6,%7}, {%8,%9}, {%0,%1,%2,%3};"
        : "+f"(c[0]), "+f"(c[1]), "+f"(c[2]), "+f"(c[3])
        : "r"(a[0]), "r"(a[1]), "r"(a[2]), "r"(a[3]), "r"(b0), "r"(b1));
}

static __device__ __forceinline__ void ldsm_x4(uint32_t* r, uint32_t saddr) {
    asm volatile("ldmatrix.sync.aligned.m8n8.x4.shared.b16 {%0,%1,%2,%3}, [%4];"
                 : "=r"(r[0]), "=r"(r[1]), "=r"(r[2]), "=r"(r[3]) : "r"(saddr));
}

#define CP_ASYNC16(sm, gp) \
    asm volatile("cp.async.cg.shared.global [%0], [%1], 16;" :: "r"(sm), "l"(gp))
#define CP_COMMIT() asm volatile("cp.async.commit_group;" ::: "memory")
#define CP_WAIT0() asm volatile("cp.async.wait_group 0;" ::: "memory")

// dynamic-smem layout for mgemm (bytes)
#define OFF_AHI(b) ((b) * 10240)
#define OFF_ALO(b) (20480 + (b) * 10240)
#define OFF_BHI(b) (40960 + (b) * 5120)
#define OFF_BLO(b) (51200 + (b) * 5120)
#define OFF_BIAS 61440
#define OFF_TRA 61696
#define OFF_TRB 62720
#define MG_SMEM 63744

// ---------------- atom encoder ----------------
__global__ void atom_kernel(const int* __restrict__ x, const float* __restrict__ emb,
                            float* __restrict__ h) {
    int n = blockIdx.x, c = threadIdx.x;
    __shared__ int xi[9];
    if (c < 9) xi[c] = x[n * 9 + c];
    __syncthreads();
    float s = 0.f;
#pragma unroll
    for (int i = 0; i < 9; i++) s += emb[((size_t)i * 119 + xi[i]) * DD + c];
    h[(size_t)n * DD + c] = s;
}

// ---------------- CSR build ----------------
__global__ void hist_kernel(const int* __restrict__ dst, int* __restrict__ deg) {
    int e = blockIdx.x * blockDim.x + threadIdx.x;
    if (e < NE) atomicAdd(&deg[dst[e]], 1);
}

__global__ void scan_kernel(const int* __restrict__ deg, int* __restrict__ rowptr,
                            int* __restrict__ cursor) {
    __shared__ int sums[1024];
    int tid = threadIdx.x;
    const int CH = (NN + 1023) / 1024;
    int start = tid * CH;
    int s = 0;
    for (int i = 0; i < CH; i++) {
        int idx = start + i;
        if (idx < NN) s += deg[idx];
    }
    sums[tid] = s;
    __syncthreads();
    for (int off = 1; off < 1024; off <<= 1) {
        int v = (tid >= off) ? sums[tid - off] : 0;
        __syncthreads();
        sums[tid] += v;
        __syncthreads();
    }
    int run = (tid == 0) ? 0 : sums[tid - 1];
    for (int i = 0; i < CH; i++) {
        int idx = start + i;
        if (idx < NN) {
            rowptr[idx] = run;
            cursor[idx] = run;
            run += deg[idx];
        }
    }
    if (tid == 1023) rowptr[NN] = sums[1023];
}

__global__ void scatter_kernel(const int* __restrict__ dst, int* __restrict__ cursor,
                               int* __restrict__ eids) {
    int e = blockIdx.x * blockDim.x + threadIdx.x;
    if (e < NE) {
        int pos = atomicAdd(&cursor[dst[e]], 1);
        eids[pos] = e;
    }
}

// ---------------- GENConv aggregation (one warp per node, online softmax) ----------------
__global__ __launch_bounds__(256) void agg_kernel(
    const float* __restrict__ h, const float* __restrict__ bnA, const float* __restrict__ bnB,
    const int* __restrict__ src, const int* __restrict__ eattr,
    const int* __restrict__ rowptr, const int* __restrict__ eids,
    const float* __restrict__ bond, const float* __restrict__ tptr, int layer,
    float* __restrict__ hh) {
    __shared__ float sb[3 * 6 * DD];
    int tid = threadIdx.x;
    for (int i = tid; i < 3 * 6 * DD; i += blockDim.x) sb[i] = bond[i];
    __syncthreads();
    float t = __ldg(&tptr[layer]);
    int warp = blockIdx.x * (blockDim.x >> 5) + (tid >> 5);
    if (warp >= NN) return;
    int lane = tid & 31;
    bool hasBn = (bnA != nullptr);

    float A[4], B[4], h2n[4];
#pragma unroll
    for (int u = 0; u < 4; u++) {
        int c = lane + 32 * u;
        float a = hasBn ? bnA[c] : 1.f;
        float b = hasBn ? bnB[c] : 0.f;
        A[u] = a; B[u] = b;
        float v = h[(size_t)warp * DD + c];
        if (hasBn) v = fmaxf(v * a + b, 0.f);
        h2n[u] = v;
    }
    const float NEGINF = __int_as_float(0xff800000);
    float m[4] = {NEGINF, NEGINF, NEGINF, NEGINF};
    float s1[4] = {0.f, 0.f, 0.f, 0.f};
    float s2[4] = {0.f, 0.f, 0.f, 0.f};
    int e0 = rowptr[warp], e1 = rowptr[warp + 1];
    for (int e = e0; e < e1; e++) {
        int eid = eids[e];
        int s = src[eid];
        int a0 = eattr[eid * 3 + 0];
        int a1 = eattr[eid * 3 + 1];
        int a2 = eattr[eid * 3 + 2];
        const float* hs = h + (size_t)s * DD;
#pragma unroll
        for (int u = 0; u < 4; u++) {
            int c = lane + 32 * u;
            float hv = hs[c];
            if (hasBn) hv = fmaxf(hv * A[u] + B[u], 0.f);
            float ee = sb[a0 * DD + c] + sb[(6 + a1) * DD + c] + sb[(12 + a2) * DD + c];
            float msg = fmaxf(hv + ee, 0.f) + G_EPS;
            float sc = msg * t;
            if (sc > m[u]) {
                float r = __expf(m[u] - sc);
                s1[u] = s1[u] * r + 1.f;
                s2[u] = s2[u] * r + msg;
                m[u] = sc;
            } else {
                float ex = __expf(sc - m[u]);
                s1[u] += ex;
                s2[u] += msg * ex;
            }
        }
    }
#pragma unroll
    for (int u = 0; u < 4; u++) {
        float mm = s2[u] / fmaxf(s1[u], G_EPS);
        hh[(size_t)warp * DD + lane + 32 * u] = h2n[u] + mm;
    }
}

// ---------------- weight pre-transpose + bf16 hi/lo split: [L][K][N] -> [L][N][K] ------------
__global__ void splitw_kernel(const float* __restrict__ W, int K, int N, int total,
                              __nv_bfloat16* __restrict__ hiT, __nv_bfloat16* __restrict__ loT) {
    int i = blockIdx.x * blockDim.x + threadIdx.x;
    if (i >= total) return;
    int n = i % N;
    int k = (i / N) % K;
    int l = i / (N * K);
    float w = W[i];
    __nv_bfloat16 hi = __float2bfloat16_rn(w);
    float lo = w - __bfloat162float(hi);
    size_t o = ((size_t)l * N + n) * K + k;
    hiT[o] = hi;
    loT[o] = __float2bfloat16_rn(lo);
}

// ---------------- fully double-buffered bf16-split mma.sync GEMM ----------------
// C[M,N] = f(A)[M,K] @ BT^T + bias (+res); f(a) = trA ? relu(a*trA[k]+trB[k]) : a.
// CTA tile 128x64; 8 warps (4m x 2n), warp tile 32x32; K chunk 32.
// A AND B double-buffered -> ONE __syncthreads per chunk; A-store overlaps other warps' MMA.
template <int K, int N>
__global__ __launch_bounds__(256) void mgemm_kernel(
    const float* __restrict__ A, const __nv_bfloat16* __restrict__ BThi,
    const __nv_bfloat16* __restrict__ BTlo, const float* __restrict__ bias,
    const float* __restrict__ trA, const float* __restrict__ trB,
    const float* __restrict__ res, float* __restrict__ C,
    float* __restrict__ statS, float* __restrict__ statQ) {
    extern __shared__ char smem[];
    const uint32_t sb = (uint32_t)__cvta_generic_to_shared(smem);
    float* biasSm = (float*)(smem + OFF_BIAS);
    float* trASm = (float*)(smem + OFF_TRA);
    float* trBSm = (float*)(smem + OFF_TRB);

    const int t = threadIdx.x;
    const int warp = t >> 5, lane = t & 31;
    const int warpM = warp >> 1, warpN = warp & 1;
    const int gc0 = blockIdx.x * 64;
    const int growBase = blockIdx.y * 128;
    const bool hasTr = (trA != nullptr);

    if (t < 64) biasSm[t] = bias[gc0 + t];
    if (hasTr) {
        for (int i = t; i < K; i += 256) { trASm[i] = trA[i]; trBSm[i] = trB[i]; }
    }
    __syncthreads();  // init visible before ANY staging reads

    const int arow = t >> 1;
    const int aseg = t & 1;
    const int grow = growBase + arow;
    const bool rowValid = (grow < NN);
    const float* arp = A + (size_t)grow * K;

    // ldmatrix per-lane offsets (u32 units within a buffer)
    const int aLOff = (warpM * 32 + (lane & 7) + ((lane >> 3) & 1) * 8) * 20 + (lane >> 4) * 4;
    const int bLOff = (warpN * 32 + (lane & 7) + (lane >> 4) * 8) * 20 + ((lane >> 3) & 1) * 4;

    // B cp.async mapping: thread t stages row t>>2, 16B quad t&3 (hi and lo)
    const int bRow = t >> 2, bQuad = t & 3;
    const size_t bGoff = (size_t)(gc0 + bRow) * K + bQuad * 8;
    const uint32_t bSoff = (uint32_t)(bRow * 20 + bQuad * 4) * 4;

    float acc[2][4][4];
#pragma unroll
    for (int mi = 0; mi < 2; mi++)
#pragma unroll
        for (int nj = 0; nj < 4; nj++)
#pragma unroll
            for (int q = 0; q < 4; q++) acc[mi][nj][q] = 0.f;

    auto ldgA = [&](int k0, float* av) {
        if (rowValid) {
#pragma unroll
            for (int g = 0; g < 4; g++) {
                float4 v = *(const float4*)(arp + k0 + aseg * 16 + g * 4);
                av[g * 4 + 0] = v.x; av[g * 4 + 1] = v.y;
                av[g * 4 + 2] = v.z; av[g * 4 + 3] = v.w;
            }
            if (hasTr) {
#pragma unroll
                for (int j = 0; j < 16; j++) {
                    int kg = k0 + aseg * 16 + j;
                    av[j] = fmaxf(av[j] * trASm[kg] + trBSm[kg], 0.f);
                }
            }
        } else {
#pragma unroll
            for (int j = 0; j < 16; j++) av[j] = 0.f;
        }
    };
    auto stsA = [&](int buf, const float* av) {
        uint32_t hp[8], lp[8];
#pragma unroll
        for (int p = 0; p < 8; p++) {
            float a0 = av[2 * p], a1 = av[2 * p + 1];
            float h0 = __bfloat162float(__float2bfloat16_rn(a0));
            float h1 = __bfloat162float(__float2bfloat16_rn(a1));
            hp[p] = pack_bf16(h0, h1);
            lp[p] = pack_bf16(a0 - h0, a1 - h1);
        }
        uint32_t* pH = (uint32_t*)(smem + OFF_AHI(buf)) + arow * 20 + aseg * 8;
        uint32_t* pL = (uint32_t*)(smem + OFF_ALO(buf)) + arow * 20 + aseg * 8;
        *(uint4*)pH = make_uint4(hp[0], hp[1], hp[2], hp[3]);
        *(uint4*)(pH + 4) = make_uint4(hp[4], hp[5], hp[6], hp[7]);
        *(uint4*)pL = make_uint4(lp[0], lp[1], lp[2], lp[3]);
        *(uint4*)(pL + 4) = make_uint4(lp[4], lp[5], lp[6], lp[7]);
    };
    auto cpB = [&](int buf, int k0) {
        CP_ASYNC16(sb + OFF_BHI(buf) + bSoff, (const void*)(BThi + bGoff + k0));
        CP_ASYNC16(sb + OFF_BLO(buf) + bSoff, (const void*)(BTlo + bGoff + k0));
    };

    // ---- prologue: chunk 0 into buffers 0 ----
    cpB(0, 0);
    CP_COMMIT();
    {
        float av[16];
        ldgA(0, av);
        stsA(0, av);
    }
    CP_WAIT0();
    __syncthreads();

    constexpr int NCH = K / 32;
    for (int ch = 0; ch < NCH; ch++) {
        const int cur = ch & 1;
        const bool more = (ch + 1 < NCH);
        float av[16];
        if (more) {
            cpB(cur ^ 1, (ch + 1) * 32);
            CP_COMMIT();
            ldgA((ch + 1) * 32, av);
        }
        // ---- mma on current chunk (buffers cur) ----
        const uint32_t ahBase = sb + OFF_AHI(cur);
        const uint32_t alBase = sb + OFF_ALO(cur);
        const uint32_t bhBase = sb + OFF_BHI(cur);
        const uint32_t blBase = sb + OFF_BLO(cur);
#pragma unroll
        for (int ks = 0; ks < 2; ks++) {
            uint32_t ah[2][4], al[2][4];
#pragma unroll
            for (int mi = 0; mi < 2; mi++) {
                uint32_t off = (uint32_t)(aLOff + mi * 16 * 20 + ks * 8) * 4;
                ldsm_x4(ah[mi], ahBase + off);
                ldsm_x4(al[mi], alBase + off);
            }
#pragma unroll
            for (int njp = 0; njp < 2; njp++) {
                uint32_t bo = (uint32_t)(bLOff + njp * 16 * 20 + ks * 8) * 4;
                uint32_t bh[4], bl[4];
                ldsm_x4(bh, bhBase + bo);
                ldsm_x4(bl, blBase + bo);
#pragma unroll
                for (int mi = 0; mi < 2; mi++) {
                    mma16816(acc[mi][njp * 2], ah[mi], bh[0], bh[1]);
                    mma16816(acc[mi][njp * 2], ah[mi], bl[0], bl[1]);
                    mma16816(acc[mi][njp * 2], al[mi], bh[0], bh[1]);
                    mma16816(acc[mi][njp * 2 + 1], ah[mi], bh[2], bh[3]);
                    mma16816(acc[mi][njp * 2 + 1], ah[mi], bl[2], bl[3]);
                    mma16816(acc[mi][njp * 2 + 1], al[mi], bh[2], bh[3]);
                }
            }
        }
        if (more) {
            stsA(cur ^ 1, av);  // different buffer: safe while others still read cur
            CP_WAIT0();
        }
        __syncthreads();  // one barrier per chunk
    }

    // ---- epilogue: bias (+res) store + column stats ----
    const bool doStat = (statS != nullptr);
#pragma unroll
    for (int njp = 0; njp < 2; njp++)
#pragma unroll
        for (int j = 0; j < 2; j++) {
            int nj = njp * 2 + j;
            int cnl = warpN * 32 + njp * 16 + j * 8 + (lane & 3) * 2;
            int cn = gc0 + cnl;
            float b0 = biasSm[cnl], b1 = biasSm[cnl + 1];
            float se = 0.f, qe = 0.f, so = 0.f, qo = 0.f;
#pragma unroll
            for (int mi = 0; mi < 2; mi++) {
                int rA = growBase + warpM * 32 + mi * 16 + (lane >> 2);
                int rB = rA + 8;
                bool mA = (rA < NN), mB = (rB < NN);
                float v0 = acc[mi][nj][0] + b0;
                float v1 = acc[mi][nj][1] + b1;
                float v2 = acc[mi][nj][2] + b0;
                float v3 = acc[mi][nj][3] + b1;
                if (res != nullptr) {
                    if (mA) {
                        float2 rv = *(const float2*)(res + (size_t)rA * N + cn);
                        v0 += rv.x; v1 += rv.y;
                    }
                    if (mB) {
                        float2 rv = *(const float2*)(res + (size_t)rB * N + cn);
                        v2 += rv.x; v3 += rv.y;
                    }
                }
                if (mA) *(float2*)(C + (size_t)rA * N + cn) = make_float2(v0, v1);
                if (mB) *(float2*)(C + (size_t)rB * N + cn) = make_float2(v2, v3);
                if (doStat) {
                    if (mA) { se += v0; qe += v0 * v0; so += v1; qo += v1 * v1; }
                    if (mB) { se += v2; qe += v2 * v2; so += v3; qo += v3 * v3; }
                }
            }
            if (doStat) {
#pragma unroll
                for (int off = 4; off < 32; off <<= 1) {
                    se += __shfl_xor_sync(0xffffffffu, se, off);
                    qe += __shfl_xor_sync(0xffffffffu, qe, off);
                    so += __shfl_xor_sync(0xffffffffu, so, off);
                    qo += __shfl_xor_sync(0xffffffffu, qo, off);
                }
                if (lane < 4) {
                    atomicAdd(&statS[cn], se);
                    atomicAdd(&statQ[cn], qe);
                    atomicAdd(&statS[cn + 1], so);
                    atomicAdd(&statQ[cn + 1], qo);
                }
            }
        }
}

// ---------------- BN stat finalize (+ zero next-stage stat buffers) ----------------
__global__ void finalize_kernel(const float* __restrict__ sum, const float* __restrict__ sq,
                                const float* __restrict__ g, const float* __restrict__ be,
                                float* __restrict__ outA, float* __restrict__ outB, int C,
                                float* __restrict__ z1, float* __restrict__ z2, int zlen) {
    int i = threadIdx.x;
    if (sum != nullptr && i < C) {
        float mu = sum[i] * (1.f / NN);
        float var = sq[i] * (1.f / NN) - mu * mu;
        float inv = rsqrtf(var + BNEPS);
        float a = g[i] * inv;
        outA[i] = a;
        outB[i] = be[i] - mu * a;
    }
    if (z1 != nullptr) {
        for (int j = i; j < zlen; j += blockDim.x) { z1[j] = 0.f; z2[j] = 0.f; }
    }
}

// ---------------- final BN + graph mean pool ----------------
__global__ void pool_kernel(const float* __restrict__ h, const float* __restrict__ bnA,
                            const float* __restrict__ bnB, const int* __restrict__ batch,
                            float* __restrict__ hg, float* __restrict__ cnt) {
    int n = blockIdx.x, c = threadIdx.x;
    int b = batch[n];
    float v = h[(size_t)n * DD + c] * bnA[c] + bnB[c];
    atomicAdd(&hg[(size_t)b * DD + c], v);
    if (c == 0) atomicAdd(&cnt[b], 1.f);
}

__global__ void out_kernel(const float* __restrict__ hg, const float* __restrict__ cnt,
                           const float* __restrict__ predW, const float* __restrict__ predb,
                           float* __restrict__ out) {
    int g = blockIdx.x, c = threadIdx.x;
    float scale = 1.f / fmaxf(cnt[g], 1.f);
    float v = hg[(size_t)g * DD + c] * scale * predW[c];
#pragma unroll
    for (int off = 16; off; off >>= 1) v += __shfl_down_sync(0xffffffffu, v, off);
    __shared__ float ws[4];
    if ((c & 31) == 0) ws[c >> 5] = v;
    __syncthreads();
    if (c == 0) out[g] = ws[0] + ws[1] + ws[2] + ws[3] + predb[0];
}

// ---------------- host orchestration ----------------
extern "C" void kernel_launch(void* const* d_in, const int* in_sizes, int n_in,
                              void* d_out, int out_size) {
    const int*   x        = (const int*)d_in[0];
    const int*   eidx     = (const int*)d_in[1];
    const int*   eattr    = (const int*)d_in[2];
    const int*   batch    = (const int*)d_in[3];
    const float* atom_emb = (const float*)d_in[4];
    const float* bond_emb = (const float*)d_in[5];
    const float* W1 = (const float*)d_in[6];
    const float* b1 = (const float*)d_in[7];
    const float* g1 = (const float*)d_in[8];
    const float* be1 = (const float*)d_in[9];
    const float* W2 = (const float*)d_in[10];
    const float* b2 = (const float*)d_in[11];
    const float* g2 = (const float*)d_in[12];
    const float* be2 = (const float*)d_in[13];
    const float* W3 = (const float*)d_in[14];
    const float* b3 = (const float*)d_in[15];
    const float* tt = (const float*)d_in[16];
    const float* norm_g = (const float*)d_in[17];
    const float* norm_b = (const float*)d_in[18];
    const float* predW = (const float*)d_in[19];
    const float* predb = (const float*)d_in[20];
    float* out = (float*)d_out;

    const int* src = eidx;
    const int* dst = eidx + NE;

    float *hA, *hB, *hh, *y1, *y2;
    int *deg, *rowptr, *cursor, *eids;
    float *st1S, *st1Q, *st2S, *st2Q, *stHS, *stHQ;
    float *bnAh, *bnBh, *bnA1, *bnB1, *bnA2, *bnB2;
    float *hg, *cnt;
    __nv_bfloat16 *w1hi, *w1lo, *w2hi, *w2lo, *w3hi, *w3lo;
    cudaGetSymbolAddress((void**)&hA, g_hA);
    cudaGetSymbolAddress((void**)&hB, g_hB);
    cudaGetSymbolAddress((void**)&hh, g_hh);
    cudaGetSymbolAddress((void**)&y1, g_y1);
    cudaGetSymbolAddress((void**)&y2, g_y2);
    cudaGetSymbolAddress((void**)&deg, g_deg);
    cudaGetSymbolAddress((void**)&rowptr, g_rowptr);
    cudaGetSymbolAddress((void**)&cursor, g_cursor);
    cudaGetSymbolAddress((void**)&eids, g_eids);
    cudaGetSymbolAddress((void**)&st1S, g_st1S);
    cudaGetSymbolAddress((void**)&st1Q, g_st1Q);
    cudaGetSymbolAddress((void**)&st2S, g_st2S);
    cudaGetSymbolAddress((void**)&st2Q, g_st2Q);
    cudaGetSymbolAddress((void**)&stHS, g_stHS);
    cudaGetSymbolAddress((void**)&stHQ, g_stHQ);
    cudaGetSymbolAddress((void**)&bnAh, g_bnAh);
    cudaGetSymbolAddress((void**)&bnBh, g_bnBh);
    cudaGetSymbolAddress((void**)&bnA1, g_bnA1);
    cudaGetSymbolAddress((void**)&bnB1, g_bnB1);
    cudaGetSymbolAddress((void**)&bnA2, g_bnA2);
    cudaGetSymbolAddress((void**)&bnB2, g_bnB2);
    cudaGetSymbolAddress((void**)&hg, g_hg);
    cudaGetSymbolAddress((void**)&cnt, g_cnt);
    cudaGetSymbolAddress((void**)&w1hi, g_w1hi);
    cudaGetSymbolAddress((void**)&w1lo, g_w1lo);
    cudaGetSymbolAddress((void**)&w2hi, g_w2hi);
    cudaGetSymbolAddress((void**)&w2lo, g_w2lo);
    cudaGetSymbolAddress((void**)&w3hi, g_w3hi);
    cudaGetSymbolAddress((void**)&w3lo, g_w3lo);

    cudaFuncSetAttribute(mgemm_kernel<DD, HH>, cudaFuncAttributeMaxDynamicSharedMemorySize, MG_SMEM);
    cudaFuncSetAttribute(mgemm_kernel<HH, HH>, cudaFuncAttributeMaxDynamicSharedMemorySize, MG_SMEM);
    cudaFuncSetAttribute(mgemm_kernel<HH, DD>, cudaFuncAttributeMaxDynamicSharedMemorySize, MG_SMEM);

    // setup: atom encoder + CSR + weight pre-split
    atom_kernel<<<NN, 128>>>(x, atom_emb, hA);
    cudaMemsetAsync(deg, 0, NN * sizeof(int));
    hist_kernel<<<(NE + 255) / 256, 256>>>(dst, deg);
    scan_kernel<<<1, 1024>>>(deg, rowptr, cursor);
    scatter_kernel<<<(NE + 255) / 256, 256>>>(dst, cursor, eids);
    {
        int t1 = NL * DD * HH;
        splitw_kernel<<<(t1 + 255) / 256, 256>>>(W1, DD, HH, t1, w1hi, w1lo);
        int t2 = NL * HH * HH;
        splitw_kernel<<<(t2 + 255) / 256, 256>>>(W2, HH, HH, t2, w2hi, w2lo);
        int t3 = NL * HH * DD;
        splitw_kernel<<<(t3 + 255) / 256, 256>>>(W3, HH, DD, t3, w3hi, w3lo);
    }

    float* hcur = hA;
    float* hnxt = hB;
    const int MBLK = (NN + 127) / 128;  // 782
    dim3 gridH(HH / 64, MBLK);
    dim3 gridD(DD / 64, MBLK);

    for (int l = 0; l < NL; l++) {
        finalize_kernel<<<1, 256>>>(l ? stHS : nullptr, stHQ,
                                    l ? norm_g + (size_t)(l - 1) * DD : nullptr,
                                    l ? norm_b + (size_t)(l - 1) * DD : nullptr,
                                    bnAh, bnBh, DD, st1S, st1Q, HH);
        agg_kernel<<<NN / 8, 256>>>(hcur, l ? bnAh : nullptr, l ? bnBh : nullptr,
                                    src, eattr, rowptr, eids,
                                    bond_emb + (size_t)l * 3 * 6 * DD, tt, l, hh);
        mgemm_kernel<DD, HH><<<gridH, 256, MG_SMEM>>>(
            hh, w1hi + (size_t)l * HH * DD, w1lo + (size_t)l * HH * DD, b1 + (size_t)l * HH,
            nullptr, nullptr, nullptr, y1, st1S, st1Q);
        finalize_kernel<<<1, 256>>>(st1S, st1Q, g1 + (size_t)l * HH, be1 + (size_t)l * HH,
                                    bnA1, bnB1, HH, st2S, st2Q, HH);
        mgemm_kernel<HH, HH><<<gridH, 256, MG_SMEM>>>(
            y1, w2hi + (size_t)l * HH * HH, w2lo + (size_t)l * HH * HH, b2 + (size_t)l * HH,
            bnA1, bnB1, nullptr, y2, st2S, st2Q);
        finalize_kernel<<<1, 256>>>(st2S, st2Q, g2 + (size_t)l * HH, be2 + (size_t)l * HH,
                                    bnA2, bnB2, HH, stHS, stHQ, DD);
        mgemm_kernel<HH, DD><<<gridD, 256, MG_SMEM>>>(
            y2, w3hi + (size_t)l * DD * HH, w3lo + (size_t)l * DD * HH, b3 + (size_t)l * DD,
            bnA2, bnB2, l ? hcur : nullptr, hnxt, stHS, stHQ);
        float* tmp = hcur; hcur = hnxt; hnxt = tmp;
    }
    finalize_kernel<<<1, 256>>>(stHS, stHQ, norm_g + (size_t)(NL - 1) * DD,
                                norm_b + (size_t)(NL - 1) * DD, bnAh, bnBh, DD,
                                nullptr, nullptr, 0);
    cudaMemsetAsync(hg, 0, (size_t)NG * DD * sizeof(float));
    cudaMemsetAsync(cnt, 0, NG * sizeof(float));
    pool_kernel<<<NN, 128>>>(hcur, bnAh, bnBh, batch, hg, cnt);
    out_kernel<<<NG, 128>>>(hg, cnt, predW, predb, out);
}